// round 7
// baseline (speedup 1.0000x reference)
#include <cuda_runtime.h>
#include <cuda_bf16.h>

// GraphNorm, persistent ring-4 pipeline (depth-3 prefetch).
//   out = a*x + b,  a = gnw*rsqrt(var+eps), b = gnb - a*m*msc
//   var = E[x^2] - 2*(m*msc)*m + (m*msc)^2  (single sweep: sum x, sum x^2)
//
// Tile = (graph, 8-col chunk): 512x8 fp32 = 16 KB. Ring of 4 SMEM buffers;
// while tile t is reduced/normalized/stored, tiles t+1..t+3 are in flight
// via cp.async.cg. 256 thr/CTA, 3 CTAs/SM. Coeffs computed warp-redundantly
// (no third barrier). DRAM = 128 MB read + 128 MB write.

#define TILE_D    8
#define THREADS   256
#define ROW_TILE  512
#define NWARPS    (THREADS / 32)          // 8
#define NBUF      4
#define BUF_ELEMS (ROW_TILE * TILE_D)     // 4096 floats = 16 KB
#define TPR       2                       // threads per row (float4)
#define ROWSTEP   (THREADS / TPR)         // 128 rows per pass
#define NPASS     (ROW_TILE / ROWSTEP)    // 4
#define EPSV      1e-6f
#define NCTA      456                     // 3 per SM

#define SMEM_BYTES ((NBUF*BUF_ELEMS + 2*NWARPS*TILE_D) * sizeof(float))

__device__ __forceinline__ unsigned smem_u32(const void* p) {
    return (unsigned)__cvta_generic_to_shared(p);
}
__device__ __forceinline__ void cp16(unsigned dst, const void* src) {
    asm volatile("cp.async.cg.shared.global [%0], [%1], 16;" :: "r"(dst), "l"(src));
}
__device__ __forceinline__ void cp_commit() {
    asm volatile("cp.async.commit_group;");
}
template <int N> __device__ __forceinline__ void cp_wait() {
    asm volatile("cp.async.wait_group %0;" :: "n"(N));
}

__device__ __forceinline__ void acc4(float4 v, float4& s1, float4& s2) {
    s1.x += v.x; s1.y += v.y; s1.z += v.z; s1.w += v.w;
    s2.x = fmaf(v.x, v.x, s2.x);
    s2.y = fmaf(v.y, v.y, s2.y);
    s2.z = fmaf(v.z, v.z, s2.z);
    s2.w = fmaf(v.w, v.w, s2.w);
}

__global__ __launch_bounds__(THREADS, 3)
void graphnorm_kernel(const float* __restrict__ x,
                      const float* __restrict__ gnw,
                      const float* __restrict__ gnb,
                      const float* __restrict__ msc,
                      const int* __restrict__ bn,
                      float* __restrict__ out,
                      int D, int B)
{
    extern __shared__ float smem[];
    float* ps1 = smem + NBUF * BUF_ELEMS;      // [NWARPS][TILE_D]
    float* ps2 = ps1 + NWARPS * TILE_D;

    const int tid  = threadIdx.x;
    const int wid  = tid >> 5;
    const int lane = tid & 31;
    const int ncc  = D / TILE_D;               // column chunks
    const int ntiles = B * ncc;

    const int l4   = (tid & (TPR - 1)) * 4;    // 0 or 4
    const int row0 = tid / TPR;                // 0..127

    const int t0 = blockIdx.x;
    const int stride = gridDim.x;
    if (t0 >= ntiles) return;

    // prefetch cursor
    int pgP = 0; long long startP = 0; int tP = t0;

    auto prefetch = [&](int slot) {
        if (tP < ntiles) {
            const int g = tP / ncc;
            while (pgP < g) startP += (long long)bn[pgP++];
            const int cnt = bn[g];
            const int cpn = min(cnt, ROW_TILE);
            const float* xg = x + startP * (long long)D + (tP % ncc) * TILE_D;
            const float* p  = xg + (long long)row0 * D + l4;
            unsigned d = smem_u32(smem + slot * BUF_ELEMS + row0 * TILE_D + l4);
            if (cpn == ROW_TILE) {
                #pragma unroll
                for (int it = 0; it < NPASS; ++it) {
                    cp16(d, p);
                    p += (long long)ROWSTEP * D;
                    d += ROWSTEP * TILE_D * 4;
                }
            } else {
                for (int r = row0; r < cpn; r += ROWSTEP) {
                    cp16(d, p);
                    p += (long long)ROWSTEP * D;
                    d += ROWSTEP * TILE_D * 4;
                }
            }
        }
        cp_commit();
        tP += stride;
    };

    // fill pipeline: tiles i=0,1,2 into slots 0,1,2
    prefetch(0);
    prefetch(1);
    prefetch(2);

    // compute cursor
    int pgC = 0; long long startC = 0;
    int tc = t0;
    int i = 0;

    for (;;) {
        // keep depth-3: issue tile i+3 into the slot freed at iteration i-1
        prefetch((i + 3) & 3);
        cp_wait<3>();          // all but 3 newest groups done -> tile i landed
        __syncthreads();

        // metadata for tile i
        const int g = tc / ncc;
        while (pgC < g) startC += (long long)bn[pgC++];
        const int cnt = bn[g];
        const int cpn = min(cnt, ROW_TILE);
        const int cc  = tc % ncc;
        float* cb = smem + (i & 3) * BUF_ELEMS;
        const float* cxg = x + startC * (long long)D + cc * TILE_D;

        // ---- reduce ----
        float4 s1 = make_float4(0.f, 0.f, 0.f, 0.f);
        float4 s2 = make_float4(0.f, 0.f, 0.f, 0.f);
        if (cpn == ROW_TILE) {
            const float* tp = cb + row0 * TILE_D + l4;
            float4 v0 = *(const float4*)(tp + 0 * ROWSTEP * TILE_D);
            float4 v1 = *(const float4*)(tp + 1 * ROWSTEP * TILE_D);
            float4 v2 = *(const float4*)(tp + 2 * ROWSTEP * TILE_D);
            float4 v3 = *(const float4*)(tp + 3 * ROWSTEP * TILE_D);
            acc4(v0, s1, s2); acc4(v1, s1, s2);
            acc4(v2, s1, s2); acc4(v3, s1, s2);
        } else {
            for (int r = row0; r < cpn; r += ROWSTEP)
                acc4(*(const float4*)(cb + r * TILE_D + l4), s1, s2);
        }
        for (int r = ROW_TILE + row0; r < cnt; r += ROWSTEP)
            acc4(*(const float4*)(cxg + (long long)r * D + l4), s1, s2);

        #pragma unroll
        for (int off = TPR; off < 32; off <<= 1) {
            s1.x += __shfl_xor_sync(0xffffffffu, s1.x, off);
            s1.y += __shfl_xor_sync(0xffffffffu, s1.y, off);
            s1.z += __shfl_xor_sync(0xffffffffu, s1.z, off);
            s1.w += __shfl_xor_sync(0xffffffffu, s1.w, off);
            s2.x += __shfl_xor_sync(0xffffffffu, s2.x, off);
            s2.y += __shfl_xor_sync(0xffffffffu, s2.y, off);
            s2.z += __shfl_xor_sync(0xffffffffu, s2.z, off);
            s2.w += __shfl_xor_sync(0xffffffffu, s2.w, off);
        }
        if (lane < TPR) {
            *(float4*)(ps1 + wid * TILE_D + lane * 4) = s1;
            *(float4*)(ps2 + wid * TILE_D + lane * 4) = s2;
        }
        __syncthreads();

        // ---- warp-redundant coeffs (no extra barrier) ----
        float a = 0.f, b = 0.f;
        if (lane < TILE_D) {
            float t1 = 0.f, t2 = 0.f;
            #pragma unroll
            for (int k = 0; k < NWARPS; ++k) {
                t1 += ps1[k * TILE_D + lane];
                t2 += ps2[k * TILE_D + lane];
            }
            const float inv_n = 1.0f / (float)cnt;
            const float m    = t1 * inv_n;
            const float ex2  = t2 * inv_n;
            const float s    = msc[cc * TILE_D + lane];
            const float ms   = m * s;
            const float var  = ex2 - 2.f * ms * m + ms * ms;
            const float rstd = rsqrtf(var + EPSV);
            a = gnw[cc * TILE_D + lane] * rstd;
            b = gnb[cc * TILE_D + lane] - a * ms;
        }
        float4 av, bv;
        av.x = __shfl_sync(0xffffffffu, a, l4 + 0);
        av.y = __shfl_sync(0xffffffffu, a, l4 + 1);
        av.z = __shfl_sync(0xffffffffu, a, l4 + 2);
        av.w = __shfl_sync(0xffffffffu, a, l4 + 3);
        bv.x = __shfl_sync(0xffffffffu, b, l4 + 0);
        bv.y = __shfl_sync(0xffffffffu, b, l4 + 1);
        bv.z = __shfl_sync(0xffffffffu, b, l4 + 2);
        bv.w = __shfl_sync(0xffffffffu, b, l4 + 3);

        // ---- apply + store ----
        float* og = out + startC * (long long)D + cc * TILE_D;
        if (cpn == ROW_TILE) {
            const float* tp = cb + row0 * TILE_D + l4;
            float* q = og + (long long)row0 * D + l4;
            float4 v0 = *(const float4*)(tp + 0 * ROWSTEP * TILE_D);
            float4 v1 = *(const float4*)(tp + 1 * ROWSTEP * TILE_D);
            float4 v2 = *(const float4*)(tp + 2 * ROWSTEP * TILE_D);
            float4 v3 = *(const float4*)(tp + 3 * ROWSTEP * TILE_D);
            float4 o0, o1, o2, o3;
            o0.x = fmaf(av.x, v0.x, bv.x); o0.y = fmaf(av.y, v0.y, bv.y);
            o0.z = fmaf(av.z, v0.z, bv.z); o0.w = fmaf(av.w, v0.w, bv.w);
            o1.x = fmaf(av.x, v1.x, bv.x); o1.y = fmaf(av.y, v1.y, bv.y);
            o1.z = fmaf(av.z, v1.z, bv.z); o1.w = fmaf(av.w, v1.w, bv.w);
            o2.x = fmaf(av.x, v2.x, bv.x); o2.y = fmaf(av.y, v2.y, bv.y);
            o2.z = fmaf(av.z, v2.z, bv.z); o2.w = fmaf(av.w, v2.w, bv.w);
            o3.x = fmaf(av.x, v3.x, bv.x); o3.y = fmaf(av.y, v3.y, bv.y);
            o3.z = fmaf(av.z, v3.z, bv.z); o3.w = fmaf(av.w, v3.w, bv.w);
            const long long rstep = (long long)ROWSTEP * D;
            *(float4*)(q + 0 * rstep) = o0;
            *(float4*)(q + 1 * rstep) = o1;
            *(float4*)(q + 2 * rstep) = o2;
            *(float4*)(q + 3 * rstep) = o3;
        } else {
            for (int r = row0; r < cpn; r += ROWSTEP) {
                float4 v = *(const float4*)(cb + r * TILE_D + l4);
                float4 o;
                o.x = fmaf(av.x, v.x, bv.x);
                o.y = fmaf(av.y, v.y, bv.y);
                o.z = fmaf(av.z, v.z, bv.z);
                o.w = fmaf(av.w, v.w, bv.w);
                *(float4*)(og + (long long)r * D + l4) = o;
            }
        }
        for (int r = ROW_TILE + row0; r < cnt; r += ROWSTEP) {
            float4 v = *(const float4*)(cxg + (long long)r * D + l4);
            float4 o;
            o.x = fmaf(av.x, v.x, bv.x);
            o.y = fmaf(av.y, v.y, bv.y);
            o.z = fmaf(av.z, v.z, bv.z);
            o.w = fmaf(av.w, v.w, bv.w);
            *(float4*)(og + (long long)r * D + l4) = o;
        }

        if (tc + stride >= ntiles) break;
        __syncthreads();       // protect this slot before it becomes a prefetch target
        tc += stride;
        ++i;
    }
}

extern "C" void kernel_launch(void* const* d_in, const int* in_sizes, int n_in,
                              void* d_out, int out_size)
{
    const float* x   = (const float*)d_in[0];
    const float* gnw = (const float*)d_in[1];
    const float* gnb = (const float*)d_in[2];
    const float* msc = (const float*)d_in[3];
    const int*   bn  = (const int*)d_in[4];
    float* out = (float*)d_out;

    const int D = in_sizes[1];     // HIDDEN
    const int B = in_sizes[4];     // NUM_GRAPHS

    cudaFuncSetAttribute(graphnorm_kernel,
                         cudaFuncAttributeMaxDynamicSharedMemorySize,
                         (int)SMEM_BYTES);

    int ntiles = B * (D / TILE_D);
    int grid = ntiles < NCTA ? ntiles : NCTA;
    graphnorm_kernel<<<grid, THREADS, SMEM_BYTES>>>(x, gnw, gnb, msc, bn, out, D, B);
}

// round 8
// speedup vs baseline: 1.5363x; 1.5363x over previous
#include <cuda_runtime.h>
#include <cuda_bf16.h>

// GraphNorm, persistent ring-3 pipeline (depth-2 prefetch), TILE_D=16.
//   out = a*x + b,  a = gnw*rsqrt(var+eps), b = gnb - a*m*msc
//   var = E[x^2] - 2*(m*msc)*m + (m*msc)^2  (single sweep: sum x, sum x^2)
//
// Tile = (graph, 16-col chunk): 512x16 fp32 = 32 KB (64B rows: R7 showed
// 32B rows fragment L2). Ring of 3 buffers: while tile i is computed,
// tiles i+1 and i+2 are in flight via cp.async.cg. 256 thr/CTA, 2 CTAs/SM.

#define TILE_D    16
#define THREADS   256
#define ROW_TILE  512
#define NWARPS    (THREADS / 32)          // 8
#define NBUF      3
#define BUF_ELEMS (ROW_TILE * TILE_D)     // 8192 floats = 32 KB
#define TPR       4                       // threads per row (float4)
#define ROWSTEP   (THREADS / TPR)         // 64 rows per pass
#define NPASS     (ROW_TILE / ROWSTEP)    // 8
#define EPSV      1e-6f
#define NCTA      304                     // 2 per SM x 152 SMs

#define SMEM_BYTES ((NBUF*BUF_ELEMS + 2*NWARPS*TILE_D) * sizeof(float))

__device__ __forceinline__ unsigned smem_u32(const void* p) {
    return (unsigned)__cvta_generic_to_shared(p);
}
__device__ __forceinline__ void cp16(unsigned dst, const void* src) {
    asm volatile("cp.async.cg.shared.global [%0], [%1], 16;" :: "r"(dst), "l"(src));
}
__device__ __forceinline__ void cp_commit() {
    asm volatile("cp.async.commit_group;");
}
template <int N> __device__ __forceinline__ void cp_wait() {
    asm volatile("cp.async.wait_group %0;" :: "n"(N));
}

__device__ __forceinline__ void acc4(float4 v, float4& s1, float4& s2) {
    s1.x += v.x; s1.y += v.y; s1.z += v.z; s1.w += v.w;
    s2.x = fmaf(v.x, v.x, s2.x);
    s2.y = fmaf(v.y, v.y, s2.y);
    s2.z = fmaf(v.z, v.z, s2.z);
    s2.w = fmaf(v.w, v.w, s2.w);
}

__global__ __launch_bounds__(THREADS, 2)
void graphnorm_kernel(const float* __restrict__ x,
                      const float* __restrict__ gnw,
                      const float* __restrict__ gnb,
                      const float* __restrict__ msc,
                      const int* __restrict__ bn,
                      float* __restrict__ out,
                      int D, int B)
{
    extern __shared__ float smem[];
    float* ps1 = smem + NBUF * BUF_ELEMS;      // [NWARPS][TILE_D]
    float* ps2 = ps1 + NWARPS * TILE_D;

    const int tid  = threadIdx.x;
    const int wid  = tid >> 5;
    const int lane = tid & 31;
    const int ncc  = D / TILE_D;
    const int ntiles = B * ncc;

    const int l4   = (tid & (TPR - 1)) * 4;    // 0,4,8,12
    const int row0 = tid / TPR;                // 0..63

    const int t0 = blockIdx.x;
    const int stride = gridDim.x;
    if (t0 >= ntiles) return;

    // ---------- prefetch cursor state ----------
    int pgP = 0; long long startP = 0; int tP = t0;

    // ---------- prefetch tile tP into 'slot' (straight-line, no lambda) ----
#define PREFETCH(slot)                                                        \
    do {                                                                      \
        if (tP < ntiles) {                                                    \
            const int gP = tP / ncc;                                          \
            while (pgP < gP) startP += (long long)bn[pgP++];                  \
            const int cntP = bn[gP];                                          \
            const int cpnP = min(cntP, ROW_TILE);                             \
            const float* pp = x + startP * (long long)D                       \
                              + (tP % ncc) * TILE_D                           \
                              + (long long)row0 * D + l4;                     \
            unsigned dd = smem_u32(smem + (slot) * BUF_ELEMS                  \
                                   + row0 * TILE_D + l4);                     \
            if (cpnP == ROW_TILE) {                                           \
                _Pragma("unroll")                                             \
                for (int it = 0; it < NPASS; ++it) {                          \
                    cp16(dd, pp);                                             \
                    pp += (long long)ROWSTEP * D;                             \
                    dd += ROWSTEP * TILE_D * 4;                               \
                }                                                             \
            } else {                                                          \
                for (int r = row0; r < cpnP; r += ROWSTEP) {                  \
                    cp16(dd, pp);                                             \
                    pp += (long long)ROWSTEP * D;                             \
                    dd += ROWSTEP * TILE_D * 4;                               \
                }                                                             \
            }                                                                 \
        }                                                                     \
        cp_commit();                                                          \
        tP += stride;                                                         \
    } while (0)

    // fill pipeline: tiles t0, t0+stride into slots 0, 1
    PREFETCH(0);
    PREFETCH(1);

    // compute cursor
    int pgC = 0; long long startC = 0;
    int tc = t0;
    int i = 0;

    for (;;) {
        // issue tile i+2 into the slot freed at iteration i-1
        PREFETCH((i + 2) % NBUF);
        cp_wait<2>();          // all but 2 newest groups done -> tile i landed
        __syncthreads();

        // metadata for tile i
        const int g = tc / ncc;
        while (pgC < g) startC += (long long)bn[pgC++];
        const int cnt = bn[g];
        const int cpn = min(cnt, ROW_TILE);
        const int cc  = tc % ncc;
        float* cb = smem + (i % NBUF) * BUF_ELEMS;
        const float* cxg = x + startC * (long long)D + cc * TILE_D;

        // ---- reduce ----
        float4 s1 = make_float4(0.f, 0.f, 0.f, 0.f);
        float4 s2 = make_float4(0.f, 0.f, 0.f, 0.f);
        if (cpn == ROW_TILE) {
            const float* tp = cb + row0 * TILE_D + l4;
            #pragma unroll
            for (int it = 0; it < NPASS; it += 4) {
                float4 v0 = *(const float4*)(tp + (it + 0) * ROWSTEP * TILE_D);
                float4 v1 = *(const float4*)(tp + (it + 1) * ROWSTEP * TILE_D);
                float4 v2 = *(const float4*)(tp + (it + 2) * ROWSTEP * TILE_D);
                float4 v3 = *(const float4*)(tp + (it + 3) * ROWSTEP * TILE_D);
                acc4(v0, s1, s2); acc4(v1, s1, s2);
                acc4(v2, s1, s2); acc4(v3, s1, s2);
            }
        } else {
            for (int r = row0; r < cpn; r += ROWSTEP)
                acc4(*(const float4*)(cb + r * TILE_D + l4), s1, s2);
        }
        for (int r = ROW_TILE + row0; r < cnt; r += ROWSTEP)
            acc4(*(const float4*)(cxg + (long long)r * D + l4), s1, s2);

        #pragma unroll
        for (int off = TPR; off < 32; off <<= 1) {
            s1.x += __shfl_xor_sync(0xffffffffu, s1.x, off);
            s1.y += __shfl_xor_sync(0xffffffffu, s1.y, off);
            s1.z += __shfl_xor_sync(0xffffffffu, s1.z, off);
            s1.w += __shfl_xor_sync(0xffffffffu, s1.w, off);
            s2.x += __shfl_xor_sync(0xffffffffu, s2.x, off);
            s2.y += __shfl_xor_sync(0xffffffffu, s2.y, off);
            s2.z += __shfl_xor_sync(0xffffffffu, s2.z, off);
            s2.w += __shfl_xor_sync(0xffffffffu, s2.w, off);
        }
        if (lane < TPR) {
            *(float4*)(ps1 + wid * TILE_D + lane * 4) = s1;
            *(float4*)(ps2 + wid * TILE_D + lane * 4) = s2;
        }
        __syncthreads();

        // ---- warp-redundant coeffs (no extra barrier) ----
        float a = 0.f, b = 0.f;
        if (lane < TILE_D) {
            float t1 = 0.f, t2 = 0.f;
            #pragma unroll
            for (int k = 0; k < NWARPS; ++k) {
                t1 += ps1[k * TILE_D + lane];
                t2 += ps2[k * TILE_D + lane];
            }
            const float inv_n = 1.0f / (float)cnt;
            const float m    = t1 * inv_n;
            const float ex2  = t2 * inv_n;
            const float s    = msc[cc * TILE_D + lane];
            const float ms   = m * s;
            const float var  = ex2 - 2.f * ms * m + ms * ms;
            const float rstd = rsqrtf(var + EPSV);
            a = gnw[cc * TILE_D + lane] * rstd;
            b = gnb[cc * TILE_D + lane] - a * ms;
        }
        float4 av, bv;
        av.x = __shfl_sync(0xffffffffu, a, l4 + 0);
        av.y = __shfl_sync(0xffffffffu, a, l4 + 1);
        av.z = __shfl_sync(0xffffffffu, a, l4 + 2);
        av.w = __shfl_sync(0xffffffffu, a, l4 + 3);
        bv.x = __shfl_sync(0xffffffffu, b, l4 + 0);
        bv.y = __shfl_sync(0xffffffffu, b, l4 + 1);
        bv.z = __shfl_sync(0xffffffffu, b, l4 + 2);
        bv.w = __shfl_sync(0xffffffffu, b, l4 + 3);

        // ---- apply + store ----
        float* og = out + startC * (long long)D + cc * TILE_D;
        if (cpn == ROW_TILE) {
            const float* tp = cb + row0 * TILE_D + l4;
            float* q = og + (long long)row0 * D + l4;
            const long long rstep = (long long)ROWSTEP * D;
            #pragma unroll
            for (int it = 0; it < NPASS; it += 4) {
                float4 v0 = *(const float4*)(tp + (it + 0) * ROWSTEP * TILE_D);
                float4 v1 = *(const float4*)(tp + (it + 1) * ROWSTEP * TILE_D);
                float4 v2 = *(const float4*)(tp + (it + 2) * ROWSTEP * TILE_D);
                float4 v3 = *(const float4*)(tp + (it + 3) * ROWSTEP * TILE_D);
                float4 o0, o1, o2, o3;
                o0.x = fmaf(av.x, v0.x, bv.x); o0.y = fmaf(av.y, v0.y, bv.y);
                o0.z = fmaf(av.z, v0.z, bv.z); o0.w = fmaf(av.w, v0.w, bv.w);
                o1.x = fmaf(av.x, v1.x, bv.x); o1.y = fmaf(av.y, v1.y, bv.y);
                o1.z = fmaf(av.z, v1.z, bv.z); o1.w = fmaf(av.w, v1.w, bv.w);
                o2.x = fmaf(av.x, v2.x, bv.x); o2.y = fmaf(av.y, v2.y, bv.y);
                o2.z = fmaf(av.z, v2.z, bv.z); o2.w = fmaf(av.w, v2.w, bv.w);
                o3.x = fmaf(av.x, v3.x, bv.x); o3.y = fmaf(av.y, v3.y, bv.y);
                o3.z = fmaf(av.z, v3.z, bv.z); o3.w = fmaf(av.w, v3.w, bv.w);
                *(float4*)(q + (it + 0) * rstep) = o0;
                *(float4*)(q + (it + 1) * rstep) = o1;
                *(float4*)(q + (it + 2) * rstep) = o2;
                *(float4*)(q + (it + 3) * rstep) = o3;
            }
        } else {
            for (int r = row0; r < cpn; r += ROWSTEP) {
                float4 v = *(const float4*)(cb + r * TILE_D + l4);
                float4 o;
                o.x = fmaf(av.x, v.x, bv.x);
                o.y = fmaf(av.y, v.y, bv.y);
                o.z = fmaf(av.z, v.z, bv.z);
                o.w = fmaf(av.w, v.w, bv.w);
                *(float4*)(og + (long long)r * D + l4) = o;
            }
        }
        for (int r = ROW_TILE + row0; r < cnt; r += ROWSTEP) {
            float4 v = *(const float4*)(cxg + (long long)r * D + l4);
            float4 o;
            o.x = fmaf(av.x, v.x, bv.x);
            o.y = fmaf(av.y, v.y, bv.y);
            o.z = fmaf(av.z, v.z, bv.z);
            o.w = fmaf(av.w, v.w, bv.w);
            *(float4*)(og + (long long)r * D + l4) = o;
        }

        if (tc + stride >= ntiles) break;
        __syncthreads();   // this slot becomes a prefetch target next iteration
        tc += stride;
        ++i;
    }
#undef PREFETCH
}

extern "C" void kernel_launch(void* const* d_in, const int* in_sizes, int n_in,
                              void* d_out, int out_size)
{
    const float* x   = (const float*)d_in[0];
    const float* gnw = (const float*)d_in[1];
    const float* gnb = (const float*)d_in[2];
    const float* msc = (const float*)d_in[3];
    const int*   bn  = (const int*)d_in[4];
    float* out = (float*)d_out;

    const int D = in_sizes[1];     // HIDDEN
    const int B = in_sizes[4];     // NUM_GRAPHS

    cudaFuncSetAttribute(graphnorm_kernel,
                         cudaFuncAttributeMaxDynamicSharedMemorySize,
                         (int)SMEM_BYTES);

    int ntiles = B * (D / TILE_D);
    int grid = ntiles < NCTA ? ntiles : NCTA;
    graphnorm_kernel<<<grid, THREADS, SMEM_BYTES>>>(x, gnw, gnb, msc, bn, out, D, B);
}

// round 9
// speedup vs baseline: 1.6662x; 1.0846x over previous
#include <cuda_runtime.h>
#include <cuda_bf16.h>

// GraphNorm, persistent double-buffered cp.async pipeline (R5 config) with
// streaming stores and 3-barrier tiles.
//   out = a*x + b,  a = gnw*rsqrt(var+eps), b = gnb - a*m*msc
//   var = E[x^2] - 2*(m*msc)*m + (m*msc)^2  (single sweep)
//
// Tile = (graph, 16-col chunk): 512x16 fp32 = 32 KB (64B rows).
// 256 thr/CTA, 3 CTAs/SM, 456 persistent CTAs; tile t+1 prefetched while
// tile t is reduced/normalized/stored. Stores use st.global.cs (evict-first)
// so the 128 MB write stream does not pollute L2.

#define TILE_D    16
#define THREADS   256
#define ROW_TILE  512
#define NWARPS    (THREADS / 32)          // 8
#define BUF_ELEMS (ROW_TILE * TILE_D)     // 8192 floats = 32 KB
#define TPR       4                       // threads per row (float4)
#define ROWSTEP   (THREADS / TPR)         // 64 rows per pass
#define NPASS     (ROW_TILE / ROWSTEP)    // 8
#define EPSV      1e-6f
#define NCTA      456                     // 3 per SM x 152 SMs

#define SMEM_BYTES ((2*BUF_ELEMS + 2*NWARPS*TILE_D) * sizeof(float))

__device__ __forceinline__ unsigned smem_u32(const void* p) {
    return (unsigned)__cvta_generic_to_shared(p);
}
__device__ __forceinline__ void cp16(unsigned dst, const void* src) {
    asm volatile("cp.async.cg.shared.global [%0], [%1], 16;" :: "r"(dst), "l"(src));
}
__device__ __forceinline__ void cp_commit() {
    asm volatile("cp.async.commit_group;");
}
template <int N> __device__ __forceinline__ void cp_wait() {
    asm volatile("cp.async.wait_group %0;" :: "n"(N));
}

__device__ __forceinline__ void acc4(float4 v, float4& s1, float4& s2) {
    s1.x += v.x; s1.y += v.y; s1.z += v.z; s1.w += v.w;
    s2.x = fmaf(v.x, v.x, s2.x);
    s2.y = fmaf(v.y, v.y, s2.y);
    s2.z = fmaf(v.z, v.z, s2.z);
    s2.w = fmaf(v.w, v.w, s2.w);
}

__global__ __launch_bounds__(THREADS, 3)
void graphnorm_kernel(const float* __restrict__ x,
                      const float* __restrict__ gnw,
                      const float* __restrict__ gnb,
                      const float* __restrict__ msc,
                      const int* __restrict__ bn,
                      float* __restrict__ out,
                      int D, int B)
{
    extern __shared__ float smem[];
    float* buf0 = smem;
    float* buf1 = smem + BUF_ELEMS;
    float* ps1  = smem + 2 * BUF_ELEMS;       // [NWARPS][TILE_D]
    float* ps2  = ps1 + NWARPS * TILE_D;

    const int tid  = threadIdx.x;
    const int wid  = tid >> 5;
    const int lane = tid & 31;
    const int ncc  = D / TILE_D;
    const int ntiles = B * ncc;

    const int l4   = (tid & (TPR - 1)) * 4;   // 0,4,8,12
    const int row0 = tid / TPR;               // 0..63

    int t = blockIdx.x;
    const int stride = gridDim.x;
    if (t >= ntiles) return;

    int pg = 0;
    long long pstart = 0;

    // ---- prefetch first tile into buf0 ----
    int g = t / ncc;
    while (pg < g) pstart += (long long)bn[pg++];
    int cnt = bn[g];
    int cpn = min(cnt, ROW_TILE);
    const float* xg = x + pstart * (long long)D + (t % ncc) * TILE_D;
    {
        const float* p = xg + (long long)row0 * D + l4;
        unsigned d = smem_u32(buf0 + row0 * TILE_D + l4);
        if (cpn == ROW_TILE) {
            #pragma unroll
            for (int it = 0; it < NPASS; ++it) {
                cp16(d, p);
                p += (long long)ROWSTEP * D;
                d += ROWSTEP * TILE_D * 4;
            }
        } else {
            for (int r = row0; r < cpn; r += ROWSTEP) {
                cp16(d, p);
                p += (long long)ROWSTEP * D;
                d += ROWSTEP * TILE_D * 4;
            }
        }
    }
    cp_commit();

    int bsel = 0;
    for (;;) {
        const long long cstart = pstart;
        const int   ccnt = cnt, ccpn = cpn;
        const int   cc   = t % ncc;
        const float* cxg = xg;
        float* cb = bsel ? buf1 : buf0;

        // ---- prefetch next tile into the other buffer ----
        const int tn = t + stride;
        const bool has_next = (tn < ntiles);
        if (has_next) {
            const int gn = tn / ncc;
            while (pg < gn) pstart += (long long)bn[pg++];
            cnt = bn[gn];
            cpn = min(cnt, ROW_TILE);
            xg = x + pstart * (long long)D + (tn % ncc) * TILE_D;
            const float* p = xg + (long long)row0 * D + l4;
            unsigned d = smem_u32((bsel ? buf0 : buf1) + row0 * TILE_D + l4);
            if (cpn == ROW_TILE) {
                #pragma unroll
                for (int it = 0; it < NPASS; ++it) {
                    cp16(d, p);
                    p += (long long)ROWSTEP * D;
                    d += ROWSTEP * TILE_D * 4;
                }
            } else {
                for (int r = row0; r < cpn; r += ROWSTEP) {
                    cp16(d, p);
                    p += (long long)ROWSTEP * D;
                    d += ROWSTEP * TILE_D * 4;
                }
            }
            cp_commit();
            cp_wait<1>();    // current tile landed; next stays in flight
        } else {
            cp_wait<0>();
        }
        __syncthreads();     // (1) tile visible to all warps

        // ---- reduce current tile ----
        float4 s1 = make_float4(0.f, 0.f, 0.f, 0.f);
        float4 s2 = make_float4(0.f, 0.f, 0.f, 0.f);
        if (ccpn == ROW_TILE) {
            const float* tp = cb + row0 * TILE_D + l4;
            #pragma unroll
            for (int it = 0; it < NPASS; it += 4) {
                float4 v0 = *(const float4*)(tp + (it + 0) * ROWSTEP * TILE_D);
                float4 v1 = *(const float4*)(tp + (it + 1) * ROWSTEP * TILE_D);
                float4 v2 = *(const float4*)(tp + (it + 2) * ROWSTEP * TILE_D);
                float4 v3 = *(const float4*)(tp + (it + 3) * ROWSTEP * TILE_D);
                acc4(v0, s1, s2); acc4(v1, s1, s2);
                acc4(v2, s1, s2); acc4(v3, s1, s2);
            }
        } else {
            for (int r = row0; r < ccpn; r += ROWSTEP)
                acc4(*(const float4*)(cb + r * TILE_D + l4), s1, s2);
        }
        for (int r = ROW_TILE + row0; r < ccnt; r += ROWSTEP)
            acc4(*(const float4*)(cxg + (long long)r * D + l4), s1, s2);

        #pragma unroll
        for (int off = TPR; off < 32; off <<= 1) {
            s1.x += __shfl_xor_sync(0xffffffffu, s1.x, off);
            s1.y += __shfl_xor_sync(0xffffffffu, s1.y, off);
            s1.z += __shfl_xor_sync(0xffffffffu, s1.z, off);
            s1.w += __shfl_xor_sync(0xffffffffu, s1.w, off);
            s2.x += __shfl_xor_sync(0xffffffffu, s2.x, off);
            s2.y += __shfl_xor_sync(0xffffffffu, s2.y, off);
            s2.z += __shfl_xor_sync(0xffffffffu, s2.z, off);
            s2.w += __shfl_xor_sync(0xffffffffu, s2.w, off);
        }
        if (lane < TPR) {
            *(float4*)(ps1 + wid * TILE_D + lane * 4) = s1;
            *(float4*)(ps2 + wid * TILE_D + lane * 4) = s2;
        }
        __syncthreads();     // (2) partials visible

        // ---- warp-redundant coeffs, shfl broadcast (no barrier) ----
        float a = 0.f, b = 0.f;
        if (lane < TILE_D) {
            float t1 = 0.f, t2 = 0.f;
            #pragma unroll
            for (int k = 0; k < NWARPS; ++k) {
                t1 += ps1[k * TILE_D + lane];
                t2 += ps2[k * TILE_D + lane];
            }
            const float inv_n = 1.0f / (float)ccnt;
            const float m    = t1 * inv_n;
            const float ex2  = t2 * inv_n;
            const float s    = msc[cc * TILE_D + lane];
            const float ms   = m * s;
            const float var  = ex2 - 2.f * ms * m + ms * ms;
            const float rstd = rsqrtf(var + EPSV);
            a = gnw[cc * TILE_D + lane] * rstd;
            b = gnb[cc * TILE_D + lane] - a * ms;
        }
        float4 av, bv;
        av.x = __shfl_sync(0xffffffffu, a, l4 + 0);
        av.y = __shfl_sync(0xffffffffu, a, l4 + 1);
        av.z = __shfl_sync(0xffffffffu, a, l4 + 2);
        av.w = __shfl_sync(0xffffffffu, a, l4 + 3);
        bv.x = __shfl_sync(0xffffffffu, b, l4 + 0);
        bv.y = __shfl_sync(0xffffffffu, b, l4 + 1);
        bv.z = __shfl_sync(0xffffffffu, b, l4 + 2);
        bv.w = __shfl_sync(0xffffffffu, b, l4 + 3);

        // ---- apply + streaming store (evict-first: out never re-read) ----
        float* og = out + cstart * (long long)D + cc * TILE_D;
        if (ccpn == ROW_TILE) {
            const float* tp = cb + row0 * TILE_D + l4;
            float* q = og + (long long)row0 * D + l4;
            const long long rstep = (long long)ROWSTEP * D;
            #pragma unroll
            for (int it = 0; it < NPASS; it += 4) {
                float4 v0 = *(const float4*)(tp + (it + 0) * ROWSTEP * TILE_D);
                float4 v1 = *(const float4*)(tp + (it + 1) * ROWSTEP * TILE_D);
                float4 v2 = *(const float4*)(tp + (it + 2) * ROWSTEP * TILE_D);
                float4 v3 = *(const float4*)(tp + (it + 3) * ROWSTEP * TILE_D);
                float4 o0, o1, o2, o3;
                o0.x = fmaf(av.x, v0.x, bv.x); o0.y = fmaf(av.y, v0.y, bv.y);
                o0.z = fmaf(av.z, v0.z, bv.z); o0.w = fmaf(av.w, v0.w, bv.w);
                o1.x = fmaf(av.x, v1.x, bv.x); o1.y = fmaf(av.y, v1.y, bv.y);
                o1.z = fmaf(av.z, v1.z, bv.z); o1.w = fmaf(av.w, v1.w, bv.w);
                o2.x = fmaf(av.x, v2.x, bv.x); o2.y = fmaf(av.y, v2.y, bv.y);
                o2.z = fmaf(av.z, v2.z, bv.z); o2.w = fmaf(av.w, v2.w, bv.w);
                o3.x = fmaf(av.x, v3.x, bv.x); o3.y = fmaf(av.y, v3.y, bv.y);
                o3.z = fmaf(av.z, v3.z, bv.z); o3.w = fmaf(av.w, v3.w, bv.w);
                __stcs((float4*)(q + (it + 0) * rstep), o0);
                __stcs((float4*)(q + (it + 1) * rstep), o1);
                __stcs((float4*)(q + (it + 2) * rstep), o2);
                __stcs((float4*)(q + (it + 3) * rstep), o3);
            }
        } else {
            for (int r = row0; r < ccpn; r += ROWSTEP) {
                float4 v = *(const float4*)(cb + r * TILE_D + l4);
                float4 o;
                o.x = fmaf(av.x, v.x, bv.x);
                o.y = fmaf(av.y, v.y, bv.y);
                o.z = fmaf(av.z, v.z, bv.z);
                o.w = fmaf(av.w, v.w, bv.w);
                __stcs((float4*)(og + (long long)r * D + l4), o);
            }
        }
        for (int r = ROW_TILE + row0; r < ccnt; r += ROWSTEP) {
            float4 v = *(const float4*)(cxg + (long long)r * D + l4);
            float4 o;
            o.x = fmaf(av.x, v.x, bv.x);
            o.y = fmaf(av.y, v.y, bv.y);
            o.z = fmaf(av.z, v.z, bv.z);
            o.w = fmaf(av.w, v.w, bv.w);
            __stcs((float4*)(og + (long long)r * D + l4), o);
        }

        if (!has_next) break;
        __syncthreads();     // (3) cb becomes prefetch target next iteration
        t = tn;
        bsel ^= 1;
    }
}

extern "C" void kernel_launch(void* const* d_in, const int* in_sizes, int n_in,
                              void* d_out, int out_size)
{
    const float* x   = (const float*)d_in[0];
    const float* gnw = (const float*)d_in[1];
    const float* gnb = (const float*)d_in[2];
    const float* msc = (const float*)d_in[3];
    const int*   bn  = (const int*)d_in[4];
    float* out = (float*)d_out;

    const int D = in_sizes[1];     // HIDDEN
    const int B = in_sizes[4];     // NUM_GRAPHS

    cudaFuncSetAttribute(graphnorm_kernel,
                         cudaFuncAttributeMaxDynamicSharedMemorySize,
                         (int)SMEM_BYTES);

    int ntiles = B * (D / TILE_D);
    int grid = ntiles < NCTA ? ntiles : NCTA;
    graphnorm_kernel<<<grid, THREADS, SMEM_BYTES>>>(x, gnw, gnb, msc, bn, out, D, B);
}

// round 10
// speedup vs baseline: 1.7211x; 1.0329x over previous
#include <cuda_runtime.h>
#include <cuda_bf16.h>

// GraphNorm, persistent double-buffered cp.async pipeline, 2 barriers/tile.
//   out = a*x + b,  a = gnw*rsqrt(var+eps), b = gnb - a*m*msc
//   var = E[x^2] - 2*(m*msc)*m + (m*msc)^2  (single sweep)
//
// Tile = (graph, 16-col chunk): 512x16 fp32 = 32 KB (64B rows).
// 256 thr/CTA, 3 CTAs/SM, 456 persistent CTAs. Prefetch of tile t+1 is
// issued AFTER barrier (1) of tile t — that barrier already proves all
// warps finished tile t-1's apply reads of the target buffer, so the old
// post-store barrier is redundant. Stores are st.global.cs (evict-first).

#define TILE_D    16
#define THREADS   256
#define ROW_TILE  512
#define NWARPS    (THREADS / 32)          // 8
#define BUF_ELEMS (ROW_TILE * TILE_D)     // 8192 floats = 32 KB
#define TPR       4                       // threads per row (float4)
#define ROWSTEP   (THREADS / TPR)         // 64 rows per pass
#define NPASS     (ROW_TILE / ROWSTEP)    // 8
#define EPSV      1e-6f
#define NCTA      456                     // 3 per SM x 152 SMs

#define SMEM_BYTES ((2*BUF_ELEMS + 2*NWARPS*TILE_D) * sizeof(float))

__device__ __forceinline__ unsigned smem_u32(const void* p) {
    return (unsigned)__cvta_generic_to_shared(p);
}
__device__ __forceinline__ void cp16(unsigned dst, const void* src) {
    asm volatile("cp.async.cg.shared.global [%0], [%1], 16;" :: "r"(dst), "l"(src));
}
__device__ __forceinline__ void cp_commit() {
    asm volatile("cp.async.commit_group;");
}
template <int N> __device__ __forceinline__ void cp_wait() {
    asm volatile("cp.async.wait_group %0;" :: "n"(N));
}

__device__ __forceinline__ void acc4(float4 v, float4& s1, float4& s2) {
    s1.x += v.x; s1.y += v.y; s1.z += v.z; s1.w += v.w;
    s2.x = fmaf(v.x, v.x, s2.x);
    s2.y = fmaf(v.y, v.y, s2.y);
    s2.z = fmaf(v.z, v.z, s2.z);
    s2.w = fmaf(v.w, v.w, s2.w);
}

__global__ __launch_bounds__(THREADS, 3)
void graphnorm_kernel(const float* __restrict__ x,
                      const float* __restrict__ gnw,
                      const float* __restrict__ gnb,
                      const float* __restrict__ msc,
                      const int* __restrict__ bn,
                      float* __restrict__ out,
                      int D, int B)
{
    extern __shared__ float smem[];
    float* buf0 = smem;
    float* buf1 = smem + BUF_ELEMS;
    float* ps1  = smem + 2 * BUF_ELEMS;       // [NWARPS][TILE_D]
    float* ps2  = ps1 + NWARPS * TILE_D;

    const int tid  = threadIdx.x;
    const int wid  = tid >> 5;
    const int lane = tid & 31;
    const int ncc  = D / TILE_D;
    const int ntiles = B * ncc;

    const int l4   = (tid & (TPR - 1)) * 4;   // 0,4,8,12
    const int row0 = tid / TPR;               // 0..63

    int t = blockIdx.x;
    const int stride = gridDim.x;
    if (t >= ntiles) return;

    // prefix cursor over batch_num (graph ids nondecreasing in t)
    int pg = 0;
    long long pstart = 0;

    // straight-line prefetch of tile (g/cnt/cpn/xg already resolved)
#define ISSUE_TILE(dstbuf, XG, CPN)                                           \
    do {                                                                      \
        const float* pp = (XG) + (long long)row0 * D + l4;                    \
        unsigned dd = smem_u32((dstbuf) + row0 * TILE_D + l4);                \
        if ((CPN) == ROW_TILE) {                                              \
            _Pragma("unroll")                                                 \
            for (int it = 0; it < NPASS; ++it) {                              \
                cp16(dd, pp);                                                 \
                pp += (long long)ROWSTEP * D;                                 \
                dd += ROWSTEP * TILE_D * 4;                                   \
            }                                                                 \
        } else {                                                              \
            for (int r = row0; r < (CPN); r += ROWSTEP) {                     \
                cp16(dd, pp);                                                 \
                pp += (long long)ROWSTEP * D;                                 \
                dd += ROWSTEP * TILE_D * 4;                                   \
            }                                                                 \
        }                                                                     \
        cp_commit();                                                          \
    } while (0)

    // ---- prologue: resolve + issue first tile into buf0 ----
    int g = t / ncc;
    while (pg < g) pstart += (long long)bn[pg++];
    int cnt = bn[g];
    int cpn = min(cnt, ROW_TILE);
    const float* xg = x + pstart * (long long)D + (t % ncc) * TILE_D;
    ISSUE_TILE(buf0, xg, cpn);

    int bsel = 0;
    for (;;) {
        // snapshot current tile
        const long long cstart = pstart;
        const int   ccnt = cnt, ccpn = cpn;
        const int   cc   = t % ncc;
        const float* cxg = xg;
        float* cb = bsel ? buf1 : buf0;

        // resolve next tile's metadata (off the critical path, before wait)
        const int tn = t + stride;
        const bool has_next = (tn < ntiles);
        if (has_next) {
            const int gn = tn / ncc;
            while (pg < gn) pstart += (long long)bn[pg++];
            cnt = bn[gn];
            cpn = min(cnt, ROW_TILE);
            xg = x + pstart * (long long)D + (tn % ncc) * TILE_D;
        }

        cp_wait<0>();        // current tile landed
        __syncthreads();     // (1) visible; also: all warps are past tile t-1's
                             //     apply reads, so the other buffer is free

        // issue next tile into the other buffer (stays in flight over
        // the whole compute+store window of the current tile)
        if (has_next)
            ISSUE_TILE(bsel ? buf0 : buf1, xg, cpn);

        // ---- reduce current tile ----
        float4 s1 = make_float4(0.f, 0.f, 0.f, 0.f);
        float4 s2 = make_float4(0.f, 0.f, 0.f, 0.f);
        if (ccpn == ROW_TILE) {
            const float* tp = cb + row0 * TILE_D + l4;
            #pragma unroll
            for (int it = 0; it < NPASS; it += 4) {
                float4 v0 = *(const float4*)(tp + (it + 0) * ROWSTEP * TILE_D);
                float4 v1 = *(const float4*)(tp + (it + 1) * ROWSTEP * TILE_D);
                float4 v2 = *(const float4*)(tp + (it + 2) * ROWSTEP * TILE_D);
                float4 v3 = *(const float4*)(tp + (it + 3) * ROWSTEP * TILE_D);
                acc4(v0, s1, s2); acc4(v1, s1, s2);
                acc4(v2, s1, s2); acc4(v3, s1, s2);
            }
        } else {
            for (int r = row0; r < ccpn; r += ROWSTEP)
                acc4(*(const float4*)(cb + r * TILE_D + l4), s1, s2);
        }
        for (int r = ROW_TILE + row0; r < ccnt; r += ROWSTEP)
            acc4(*(const float4*)(cxg + (long long)r * D + l4), s1, s2);

        #pragma unroll
        for (int off = TPR; off < 32; off <<= 1) {
            s1.x += __shfl_xor_sync(0xffffffffu, s1.x, off);
            s1.y += __shfl_xor_sync(0xffffffffu, s1.y, off);
            s1.z += __shfl_xor_sync(0xffffffffu, s1.z, off);
            s1.w += __shfl_xor_sync(0xffffffffu, s1.w, off);
            s2.x += __shfl_xor_sync(0xffffffffu, s2.x, off);
            s2.y += __shfl_xor_sync(0xffffffffu, s2.y, off);
            s2.z += __shfl_xor_sync(0xffffffffu, s2.z, off);
            s2.w += __shfl_xor_sync(0xffffffffu, s2.w, off);
        }
        if (lane < TPR) {
            *(float4*)(ps1 + wid * TILE_D + lane * 4) = s1;
            *(float4*)(ps2 + wid * TILE_D + lane * 4) = s2;
        }
        __syncthreads();     // (2) partials visible

        // ---- warp-redundant coeffs, shfl broadcast (no barrier) ----
        float a = 0.f, b = 0.f;
        if (lane < TILE_D) {
            float t1 = 0.f, t2 = 0.f;
            #pragma unroll
            for (int k = 0; k < NWARPS; ++k) {
                t1 += ps1[k * TILE_D + lane];
                t2 += ps2[k * TILE_D + lane];
            }
            const float inv_n = 1.0f / (float)ccnt;
            const float m    = t1 * inv_n;
            const float ex2  = t2 * inv_n;
            const float s    = msc[cc * TILE_D + lane];
            const float ms   = m * s;
            const float var  = ex2 - 2.f * ms * m + ms * ms;
            const float rstd = rsqrtf(var + EPSV);
            a = gnw[cc * TILE_D + lane] * rstd;
            b = gnb[cc * TILE_D + lane] - a * ms;
        }
        float4 av, bv;
        av.x = __shfl_sync(0xffffffffu, a, l4 + 0);
        av.y = __shfl_sync(0xffffffffu, a, l4 + 1);
        av.z = __shfl_sync(0xffffffffu, a, l4 + 2);
        av.w = __shfl_sync(0xffffffffu, a, l4 + 3);
        bv.x = __shfl_sync(0xffffffffu, b, l4 + 0);
        bv.y = __shfl_sync(0xffffffffu, b, l4 + 1);
        bv.z = __shfl_sync(0xffffffffu, b, l4 + 2);
        bv.w = __shfl_sync(0xffffffffu, b, l4 + 3);

        // ---- apply + streaming store (evict-first: out never re-read) ----
        float* og = out + cstart * (long long)D + cc * TILE_D;
        if (ccpn == ROW_TILE) {
            const float* tp = cb + row0 * TILE_D + l4;
            float* q = og + (long long)row0 * D + l4;
            const long long rstep = (long long)ROWSTEP * D;
            #pragma unroll
            for (int it = 0; it < NPASS; it += 4) {
                float4 v0 = *(const float4*)(tp + (it + 0) * ROWSTEP * TILE_D);
                float4 v1 = *(const float4*)(tp + (it + 1) * ROWSTEP * TILE_D);
                float4 v2 = *(const float4*)(tp + (it + 2) * ROWSTEP * TILE_D);
                float4 v3 = *(const float4*)(tp + (it + 3) * ROWSTEP * TILE_D);
                float4 o0, o1, o2, o3;
                o0.x = fmaf(av.x, v0.x, bv.x); o0.y = fmaf(av.y, v0.y, bv.y);
                o0.z = fmaf(av.z, v0.z, bv.z); o0.w = fmaf(av.w, v0.w, bv.w);
                o1.x = fmaf(av.x, v1.x, bv.x); o1.y = fmaf(av.y, v1.y, bv.y);
                o1.z = fmaf(av.z, v1.z, bv.z); o1.w = fmaf(av.w, v1.w, bv.w);
                o2.x = fmaf(av.x, v2.x, bv.x); o2.y = fmaf(av.y, v2.y, bv.y);
                o2.z = fmaf(av.z, v2.z, bv.z); o2.w = fmaf(av.w, v2.w, bv.w);
                o3.x = fmaf(av.x, v3.x, bv.x); o3.y = fmaf(av.y, v3.y, bv.y);
                o3.z = fmaf(av.z, v3.z, bv.z); o3.w = fmaf(av.w, v3.w, bv.w);
                __stcs((float4*)(q + (it + 0) * rstep), o0);
                __stcs((float4*)(q + (it + 1) * rstep), o1);
                __stcs((float4*)(q + (it + 2) * rstep), o2);
                __stcs((float4*)(q + (it + 3) * rstep), o3);
            }
        } else {
            for (int r = row0; r < ccpn; r += ROWSTEP) {
                float4 v = *(const float4*)(cb + r * TILE_D + l4);
                float4 o;
                o.x = fmaf(av.x, v.x, bv.x);
                o.y = fmaf(av.y, v.y, bv.y);
                o.z = fmaf(av.z, v.z, bv.z);
                o.w = fmaf(av.w, v.w, bv.w);
                __stcs((float4*)(og + (long long)r * D + l4), o);
            }
        }
        for (int r = ROW_TILE + row0; r < ccnt; r += ROWSTEP) {
            float4 v = *(const float4*)(cxg + (long long)r * D + l4);
            float4 o;
            o.x = fmaf(av.x, v.x, bv.x);
            o.y = fmaf(av.y, v.y, bv.y);
            o.z = fmaf(av.z, v.z, bv.z);
            o.w = fmaf(av.w, v.w, bv.w);
            __stcs((float4*)(og + (long long)r * D + l4), o);
        }

        if (!has_next) break;
        t = tn;
        bsel ^= 1;
    }
#undef ISSUE_TILE
}

extern "C" void kernel_launch(void* const* d_in, const int* in_sizes, int n_in,
                              void* d_out, int out_size)
{
    const float* x   = (const float*)d_in[0];
    const float* gnw = (const float*)d_in[1];
    const float* gnb = (const float*)d_in[2];
    const float* msc = (const float*)d_in[3];
    const int*   bn  = (const int*)d_in[4];
    float* out = (float*)d_out;

    const int D = in_sizes[1];     // HIDDEN
    const int B = in_sizes[4];     // NUM_GRAPHS

    cudaFuncSetAttribute(graphnorm_kernel,
                         cudaFuncAttributeMaxDynamicSharedMemorySize,
                         (int)SMEM_BYTES);

    int ntiles = B * (D / TILE_D);
    int grid = ntiles < NCTA ? ntiles : NCTA;
    graphnorm_kernel<<<grid, THREADS, SMEM_BYTES>>>(x, gnw, gnb, msc, bn, out, D, B);
}